// round 11
// baseline (speedup 1.0000x reference)
#include <cuda_runtime.h>
#include <cuda_fp16.h>
#include <cuda_fp8.h>
#include <stdint.h>
#include <math.h>

// ---------------------------------------------------------------------------
// Static scratch (no runtime allocation allowed).
// ---------------------------------------------------------------------------
#define MAX_S   (4 * 1024 * 1024)
#define MAX_NHD (8 * 1024 * 1024)
#define MAX_HB  64
#define MAX_N   (1024 * 1024)
#define MAX_E   (4 * 1024 * 1024)
__device__ __align__(16) float g_s[MAX_S];
__device__ unsigned char g_q8[MAX_NHD];
__device__ unsigned char g_k8[MAX_NHD];
__device__ float         g_bs;           // beta / sqrt(D)
__device__ float         g_ba[MAX_HB];   // beta * a[h]
__device__ float         g_coef;         // lam / beta
__device__ int           g_cnt[MAX_N];   // per-node degree (histogram)
__device__ int           g_off[MAX_N + 1]; // CSR offsets (exclusive scan)
__device__ int           g_woff[MAX_N];  // working offsets for scatter
__device__ int           g_su[MAX_E];    // u indices sorted by c

__device__ __forceinline__ float softplus_f(float x) {
    return log1pf(expf(x));
}

__device__ __forceinline__ __half2 fp8x2_to_h2(unsigned short s) {
    union { __half2_raw r; __half2 h; } cvt;
    cvt.r = __nv_cvt_fp8x2_to_halfraw2((__nv_fp8x2_storage_t)s, __NV_E4M3);
    return cvt.h;
}

// ---------------------------------------------------------------------------
// Kernel A: zero g_s/out/g_cnt, convert Q/K f32 -> e4m3, precompute scalars.
// ---------------------------------------------------------------------------
__global__ void prep_kernel(const float* __restrict__ Q,
                            const float* __restrict__ K,
                            const float* __restrict__ a,
                            const float* __restrict__ lam_raw,
                            const float* __restrict__ beta_raw,
                            float* __restrict__ out,
                            int out_size, int s_count, int total4,
                            int N, int H, int D) {
    int i = blockIdx.x * blockDim.x + threadIdx.x;
    if (i == 0) {
        float beta = fminf(softplus_f(beta_raw[0]), 10.0f);
        float lam  = softplus_f(lam_raw[0]);
        g_bs   = beta * rsqrtf((float)D);
        g_coef = lam / beta;
        int hb = H < MAX_HB ? H : MAX_HB;
        for (int h = 0; h < hb; h++) g_ba[h] = beta * a[h];
    }
    if (i < s_count) g_s[i] = 0.0f;
    if (i < out_size) out[i] = 0.0f;
    if (i < N) g_cnt[i] = 0;
    if (i >= total4) return;
    float4 q = reinterpret_cast<const float4*>(Q)[i];
    float4 k = reinterpret_cast<const float4*>(K)[i];
    unsigned int qp =
        (unsigned int)__nv_cvt_float2_to_fp8x2(make_float2(q.x, q.y), __NV_SATFINITE, __NV_E4M3) |
        ((unsigned int)__nv_cvt_float2_to_fp8x2(make_float2(q.z, q.w), __NV_SATFINITE, __NV_E4M3) << 16);
    unsigned int kp =
        (unsigned int)__nv_cvt_float2_to_fp8x2(make_float2(k.x, k.y), __NV_SATFINITE, __NV_E4M3) |
        ((unsigned int)__nv_cvt_float2_to_fp8x2(make_float2(k.z, k.w), __NV_SATFINITE, __NV_E4M3) << 16);
    reinterpret_cast<unsigned int*>(g_q8)[i] = qp;
    reinterpret_cast<unsigned int*>(g_k8)[i] = kp;
}

// ---------------------------------------------------------------------------
// Sort stage 1: histogram of destination nodes.
// ---------------------------------------------------------------------------
__global__ void hist_kernel(const int* __restrict__ c, int E) {
    int e = blockIdx.x * blockDim.x + threadIdx.x;
    if (e < E) atomicAdd(&g_cnt[c[e]], 1);
}

// ---------------------------------------------------------------------------
// Sort stage 2: single-block two-level exclusive scan of g_cnt[0..N) into
// g_off (and g_woff). 1024 threads, each owns a contiguous chunk.
// ---------------------------------------------------------------------------
__global__ void scan_kernel(int N, int E) {
    __shared__ int part[1024];
    int t = threadIdx.x;
    int chunk = (N + 1023) >> 10;
    int lo = t * chunk;
    int hi = lo + chunk; if (hi > N) hi = N;
    int s = 0;
    for (int i = lo; i < hi; i++) s += g_cnt[i];
    part[t] = s;
    __syncthreads();
    // Hillis-Steele inclusive scan
    for (int d = 1; d < 1024; d <<= 1) {
        int v = (t >= d) ? part[t - d] : 0;
        __syncthreads();
        part[t] += v;
        __syncthreads();
    }
    int run = (t > 0) ? part[t - 1] : 0;
    for (int i = lo; i < hi; i++) {
        int cnt = g_cnt[i];
        g_off[i]  = run;
        g_woff[i] = run;
        run += cnt;
    }
    if (t == 0) g_off[N] = E;
}

// ---------------------------------------------------------------------------
// Sort stage 3: scatter u into CSR order.
// ---------------------------------------------------------------------------
__global__ void scatter_kernel(const int* __restrict__ c,
                               const int* __restrict__ u, int E) {
    int e = blockIdx.x * blockDim.x + threadIdx.x;
    if (e >= E) return;
    int pos = atomicAdd(&g_woff[c[e]], 1);
    g_su[pos] = u[e];
}

// ---------------------------------------------------------------------------
// Kernel B (H=4, D=32, fp8, sorted): one warp per node.
// Q row loaded once (broadcast across groups). 4 edges per pass (8 lanes
// each), u indices buffered 32-at-a-time, K gather software-pipelined.
// Per-head exp-sums accumulate in registers; one plain store per node.
// ---------------------------------------------------------------------------
__global__ void __launch_bounds__(256) edge_sorted_kernel(int N) {
    int warp = (blockIdx.x * blockDim.x + threadIdx.x) >> 5;
    if (warp >= N) return;
    int lane = threadIdx.x & 31;
    int sub = lane >> 3;   // edge slot within a pass (0..3)
    int lw8 = lane & 7;    // lane within edge group

    int start = g_off[warp];
    int end   = g_off[warp + 1];

    // Q row chunk: same address for same lw8 in all 4 groups -> 1 line, bcast.
    uint4 qv = reinterpret_cast<const uint4*>(g_q8 + (size_t)warp * 128)[lw8];
    const unsigned int* qw = reinterpret_cast<const unsigned int*>(&qv);

    float bs = g_bs;
    int h = lw8 >> 1;
    float bah = g_ba[h];
    float sacc = 0.0f;

    if (start < end) {
        int bufbase = start;
        int myu = (start + lane < end) ? g_su[start + lane] : 0;

        int ui0 = __shfl_sync(0xffffffffu, myu, sub);
        uint4 kv = reinterpret_cast<const uint4*>(g_k8 + (size_t)ui0 * 128)[lw8];

        for (int e0 = start; e0 < end; e0 += 4) {
            // prefetch next pass's K rows
            uint4 kvn = kv;
            int e0n = e0 + 4;
            if (e0n < end) {
                int reln = e0n - bufbase + sub;   // uniform rollover (mult of 4)
                if (reln >= 32) {
                    bufbase += 32;
                    myu = (bufbase + lane < end) ? g_su[bufbase + lane] : 0;
                    reln -= 32;
                }
                int uin = __shfl_sync(0xffffffffu, myu, reln);
                kvn = reinterpret_cast<const uint4*>(g_k8 + (size_t)uin * 128)[lw8];
            }

            // compute current pass
            const unsigned int* kw = reinterpret_cast<const unsigned int*>(&kv);
            __half2 acc = __float2half2_rn(0.0f);
#pragma unroll
            for (int w = 0; w < 4; w++) {
                acc = __hfma2(fp8x2_to_h2((unsigned short)(qw[w] & 0xffff)),
                              fp8x2_to_h2((unsigned short)(kw[w] & 0xffff)), acc);
                acc = __hfma2(fp8x2_to_h2((unsigned short)(qw[w] >> 16)),
                              fp8x2_to_h2((unsigned short)(kw[w] >> 16)), acc);
            }
            float fa = __low2float(acc) + __high2float(acc);
            fa += __shfl_xor_sync(0xffffffffu, fa, 1);  // both lanes: head dot

            float ev = __expf(fmaf(fa, bs, bah));
            if ((e0 + sub) < end && ((lw8 & 1) == 0)) sacc += ev;

            kv = kvn;
        }
    }

    // merge the 4 groups
    sacc += __shfl_xor_sync(0xffffffffu, sacc, 8);
    sacc += __shfl_xor_sync(0xffffffffu, sacc, 16);
    if (sub == 0 && (lw8 & 1) == 0) {
        g_s[(size_t)warp * 4 + h] = sacc;   // plain store, no atomics
    }
}

// Generic fallback (any H, D) — f32 path, one thread per (edge, head)
__global__ void edge_kernel_g(const float* __restrict__ Q,
                              const float* __restrict__ K,
                              const float* __restrict__ a,
                              const float* __restrict__ beta_raw,
                              const int* __restrict__ c,
                              const int* __restrict__ u,
                              int E, int H, int D) {
    long long tid = (long long)blockIdx.x * blockDim.x + threadIdx.x;
    long long total = (long long)E * H;
    if (tid >= total) return;
    int e = (int)(tid / H);
    int h = (int)(tid % H);

    int ci = c[e];
    int ui = u[e];

    const float* q = Q + ((size_t)ci * H + h) * D;
    const float* k = K + ((size_t)ui * H + h) * D;
    float acc = 0.0f;
    for (int d = 0; d < D; d++) acc = fmaf(q[d], k[d], acc);

    float beta = fminf(softplus_f(beta_raw[0]), 10.0f);
    float ell = acc * rsqrtf((float)D) + a[h];
    atomicAdd(&g_s[(size_t)ci * H + h], __expf(beta * ell));
}

// ---------------------------------------------------------------------------
// Kernel C: per-node log + per-graph reduce via block-local smem.
// ---------------------------------------------------------------------------
#define MAX_GH 4096
__global__ void node_kernel_sm(const int* __restrict__ batch,
                               float* __restrict__ out,
                               int N, int H, int gh) {
    __shared__ float sred[MAX_GH];
    for (int i = threadIdx.x; i < gh; i += blockDim.x) sred[i] = 0.0f;
    __syncthreads();

    if (H == 4) {
        for (int n = blockIdx.x * blockDim.x + threadIdx.x; n < N;
             n += gridDim.x * blockDim.x) {
            float4 sv = reinterpret_cast<const float4*>(g_s)[n];
            int g = batch[n];
            float v0 = sv.x > 0.0f ? logf(sv.x) : 0.0f;
            float v1 = sv.y > 0.0f ? logf(sv.y) : 0.0f;
            float v2 = sv.z > 0.0f ? logf(sv.z) : 0.0f;
            float v3 = sv.w > 0.0f ? logf(sv.w) : 0.0f;
            atomicAdd(&sred[g * 4 + 0], v0);
            atomicAdd(&sred[g * 4 + 1], v1);
            atomicAdd(&sred[g * 4 + 2], v2);
            atomicAdd(&sred[g * 4 + 3], v3);
        }
    } else {
        for (int n = blockIdx.x * blockDim.x + threadIdx.x; n < N;
             n += gridDim.x * blockDim.x) {
            int g = batch[n];
            for (int h = 0; h < H; h++) {
                float s = g_s[(size_t)n * H + h];
                float v = s > 0.0f ? logf(s) : 0.0f;
                atomicAdd(&sred[g * H + h], v);
            }
        }
    }
    __syncthreads();
    float coef = g_coef;
    for (int i = threadIdx.x; i < gh; i += blockDim.x) {
        float v = sred[i];
        if (v != 0.0f) atomicAdd(&out[i], coef * v);
    }
}

__global__ void node_kernel_g(const int* __restrict__ batch,
                              float* __restrict__ out,
                              int N, int H) {
    int n = blockIdx.x * blockDim.x + threadIdx.x;
    if (n >= N) return;
    float coef = g_coef;
    int g = batch[n];
    for (int h = 0; h < H; h++) {
        float s = g_s[(size_t)n * H + h];
        float v = s > 0.0f ? logf(s) : 0.0f;
        atomicAdd(&out[g * H + h], coef * v);
    }
}

// ---------------------------------------------------------------------------
// Launch.  Inputs (metadata order):
//   0: G [4,4] f32 (unused)   1: Q2 [N,H,D] f32   2: K2 [N,H,D] f32
//   3: a_2 [H] f32   4: lambda_2_raw [1] f32   5: beta_2_raw [1] f32
//   6: c_2 [E] i32   7: u_2 [E] i32   8: batch [N] i32
// Output: [num_graphs, H] f32
// ---------------------------------------------------------------------------
extern "C" void kernel_launch(void* const* d_in, const int* in_sizes, int n_in,
                              void* d_out, int out_size) {
    const float* Q        = (const float*)d_in[1];
    const float* K        = (const float*)d_in[2];
    const float* a        = (const float*)d_in[3];
    const float* lam_raw  = (const float*)d_in[4];
    const float* beta_raw = (const float*)d_in[5];
    const int*   c        = (const int*)d_in[6];
    const int*   u        = (const int*)d_in[7];
    const int*   batch    = (const int*)d_in[8];
    float*       out      = (float*)d_out;

    int H = in_sizes[3];
    int E = in_sizes[6];
    int N = in_sizes[8];
    long long nhd = in_sizes[1];
    int D = (int)(nhd / ((long long)N * H));

    int s_count = N * H;
    if (s_count > MAX_S) return;

    const int TB = 256;
    bool fast = (H == 4 && D == 32 && nhd <= MAX_NHD && (nhd % 4) == 0 &&
                 N <= MAX_N && E <= MAX_E);

    if (fast) {
        int total4 = (int)(nhd / 4);
        int work = total4;
        if (s_count > work) work = s_count;
        if (out_size > work) work = out_size;
        if (N > work) work = N;
        prep_kernel<<<(work + TB - 1) / TB, TB>>>(Q, K, a, lam_raw, beta_raw,
                                                  out, out_size, s_count, total4,
                                                  N, H, D);

        hist_kernel<<<(E + TB - 1) / TB, TB>>>(c, E);
        scan_kernel<<<1, 1024>>>(N, E);
        scatter_kernel<<<(E + TB - 1) / TB, TB>>>(c, u, E);

        // warp per node
        long long threads = (long long)N * 32;
        int blocks = (int)((threads + TB - 1) / TB);
        edge_sorted_kernel<<<blocks, TB>>>(N);
    } else {
        prep_kernel<<<((s_count > out_size ? s_count : out_size) + TB - 1) / TB, TB>>>(
            Q, K, a, lam_raw, beta_raw, out, out_size, s_count, 0, 0, H, D);
        long long total = (long long)E * H;
        edge_kernel_g<<<(int)((total + TB - 1) / TB), TB>>>(Q, K, a, beta_raw, c, u, E, H, D);
    }

    if (out_size <= MAX_GH) {
        int blocks = (N + TB - 1) / TB;
        if (blocks > 120) blocks = 120;
        node_kernel_sm<<<blocks, TB>>>(batch, out, N, H, out_size);
    } else {
        node_kernel_g<<<(N + TB - 1) / TB, TB>>>(batch, out, N, H);
    }
}

// round 12
// speedup vs baseline: 1.4541x; 1.4541x over previous
#include <cuda_runtime.h>
#include <cuda_fp16.h>
#include <cuda_fp8.h>
#include <stdint.h>
#include <math.h>

// ---------------------------------------------------------------------------
// Static scratch (no runtime allocation allowed).
// ---------------------------------------------------------------------------
#define MAX_S   (4 * 1024 * 1024)
#define MAX_NHD (8 * 1024 * 1024)
#define MAX_HB  64
#define MAX_N   (1024 * 1024)
#define MAX_E   (4 * 1024 * 1024)
#define NT_SCAN 4096
__device__ __align__(16) float g_s[MAX_S];
__device__ unsigned char g_q8[MAX_NHD];
__device__ unsigned char g_k8[MAX_NHD];
__device__ float         g_bs;             // beta / sqrt(D)
__device__ float         g_ba[MAX_HB];     // beta * a[h]
__device__ float         g_coef;           // lam / beta
__device__ int           g_cnt[MAX_N];     // per-node degree
__device__ int           g_off[MAX_N + 1]; // CSR offsets
__device__ int           g_woff[MAX_N];    // working offsets for scatter
__device__ int           g_su[MAX_E];      // u indices sorted by c
__device__ int           g_tsum[NT_SCAN];  // scan stage partials
__device__ int           g_tpre[NT_SCAN];  // scan stage prefixes

__device__ __forceinline__ float softplus_f(float x) {
    return log1pf(expf(x));
}

__device__ __forceinline__ __half2 fp8x2_to_h2(unsigned short s) {
    union { __half2_raw r; __half2 h; } cvt;
    cvt.r = __nv_cvt_fp8x2_to_halfraw2((__nv_fp8x2_storage_t)s, __NV_E4M3);
    return cvt.h;
}

// ---------------------------------------------------------------------------
// Kernel A: zero g_s/out/g_cnt, convert Q/K f32 -> e4m3, precompute scalars.
// ---------------------------------------------------------------------------
__global__ void prep_kernel(const float* __restrict__ Q,
                            const float* __restrict__ K,
                            const float* __restrict__ a,
                            const float* __restrict__ lam_raw,
                            const float* __restrict__ beta_raw,
                            float* __restrict__ out,
                            int out_size, int s_count, int total4,
                            int N, int H, int D) {
    int i = blockIdx.x * blockDim.x + threadIdx.x;
    if (i == 0) {
        float beta = fminf(softplus_f(beta_raw[0]), 10.0f);
        float lam  = softplus_f(lam_raw[0]);
        g_bs   = beta * rsqrtf((float)D);
        g_coef = lam / beta;
        int hb = H < MAX_HB ? H : MAX_HB;
        for (int h = 0; h < hb; h++) g_ba[h] = beta * a[h];
    }
    if (i < s_count) g_s[i] = 0.0f;
    if (i < out_size) out[i] = 0.0f;
    if (i < N) g_cnt[i] = 0;
    if (i >= total4) return;
    float4 q = reinterpret_cast<const float4*>(Q)[i];
    float4 k = reinterpret_cast<const float4*>(K)[i];
    unsigned int qp =
        (unsigned int)__nv_cvt_float2_to_fp8x2(make_float2(q.x, q.y), __NV_SATFINITE, __NV_E4M3) |
        ((unsigned int)__nv_cvt_float2_to_fp8x2(make_float2(q.z, q.w), __NV_SATFINITE, __NV_E4M3) << 16);
    unsigned int kp =
        (unsigned int)__nv_cvt_float2_to_fp8x2(make_float2(k.x, k.y), __NV_SATFINITE, __NV_E4M3) |
        ((unsigned int)__nv_cvt_float2_to_fp8x2(make_float2(k.z, k.w), __NV_SATFINITE, __NV_E4M3) << 16);
    reinterpret_cast<unsigned int*>(g_q8)[i] = qp;
    reinterpret_cast<unsigned int*>(g_k8)[i] = kp;
}

// ---------------------------------------------------------------------------
// Sort stage 1: histogram (4 edges per thread, int4 loads, MLP=4).
// ---------------------------------------------------------------------------
__global__ void hist_kernel(const int* __restrict__ c, int E) {
    int t = blockIdx.x * blockDim.x + threadIdx.x;
    int e0 = t * 4;
    if (e0 + 3 < E) {
        int4 cv = *reinterpret_cast<const int4*>(c + e0);
        atomicAdd(&g_cnt[cv.x], 1);
        atomicAdd(&g_cnt[cv.y], 1);
        atomicAdd(&g_cnt[cv.z], 1);
        atomicAdd(&g_cnt[cv.w], 1);
    } else {
        for (int e = e0; e < E; e++) atomicAdd(&g_cnt[c[e]], 1);
    }
}

// ---------------------------------------------------------------------------
// Sort stage 2a: per-virtual-thread chunk sums (16 blocks x 256 threads).
// ---------------------------------------------------------------------------
__global__ void scan1_kernel(int N) {
    int t = blockIdx.x * blockDim.x + threadIdx.x;  // 0..NT_SCAN-1
    int chunk = (N + NT_SCAN - 1) / NT_SCAN;
    int lo = t * chunk;
    int hi = lo + chunk; if (hi > N) hi = N;
    int s = 0;
    for (int i = lo; i < hi; i++) s += g_cnt[i];
    g_tsum[t] = s;
}

// ---------------------------------------------------------------------------
// Sort stage 2b: single block scans the 4096 partials (exclusive).
// ---------------------------------------------------------------------------
__global__ void scan2_kernel() {
    __shared__ int part[1024];
    int j = threadIdx.x;             // 0..1023, owns g_tsum[4j..4j+3]
    int v0 = g_tsum[4 * j + 0];
    int v1 = g_tsum[4 * j + 1];
    int v2 = g_tsum[4 * j + 2];
    int v3 = g_tsum[4 * j + 3];
    part[j] = v0 + v1 + v2 + v3;
    __syncthreads();
    for (int d = 1; d < 1024; d <<= 1) {
        int v = (j >= d) ? part[j - d] : 0;
        __syncthreads();
        part[j] += v;
        __syncthreads();
    }
    int base = (j > 0) ? part[j - 1] : 0;
    g_tpre[4 * j + 0] = base;
    g_tpre[4 * j + 1] = base + v0;
    g_tpre[4 * j + 2] = base + v0 + v1;
    g_tpre[4 * j + 3] = base + v0 + v1 + v2;
}

// ---------------------------------------------------------------------------
// Sort stage 2c: write CSR offsets in parallel.
// ---------------------------------------------------------------------------
__global__ void scan3_kernel(int N, int E) {
    int t = blockIdx.x * blockDim.x + threadIdx.x;
    int chunk = (N + NT_SCAN - 1) / NT_SCAN;
    int lo = t * chunk;
    int hi = lo + chunk; if (hi > N) hi = N;
    int run = g_tpre[t];
    for (int i = lo; i < hi; i++) {
        int cnt = g_cnt[i];
        g_off[i]  = run;
        g_woff[i] = run;
        run += cnt;
    }
    if (t == 0) g_off[N] = E;
}

// ---------------------------------------------------------------------------
// Sort stage 3: scatter u into CSR order (4 edges per thread, MLP=4).
// ---------------------------------------------------------------------------
__global__ void scatter_kernel(const int* __restrict__ c,
                               const int* __restrict__ u, int E) {
    int t = blockIdx.x * blockDim.x + threadIdx.x;
    int e0 = t * 4;
    if (e0 + 3 < E) {
        int4 cv = *reinterpret_cast<const int4*>(c + e0);
        int4 uv = *reinterpret_cast<const int4*>(u + e0);
        int p0 = atomicAdd(&g_woff[cv.x], 1);
        int p1 = atomicAdd(&g_woff[cv.y], 1);
        int p2 = atomicAdd(&g_woff[cv.z], 1);
        int p3 = atomicAdd(&g_woff[cv.w], 1);
        g_su[p0] = uv.x;
        g_su[p1] = uv.y;
        g_su[p2] = uv.z;
        g_su[p3] = uv.w;
    } else {
        for (int e = e0; e < E; e++) {
            int pos = atomicAdd(&g_woff[c[e]], 1);
            g_su[pos] = u[e];
        }
    }
}

// ---------------------------------------------------------------------------
// Kernel B (H=4, D=32, fp8, sorted): one warp per node.
// Q row loaded once (broadcast). 4 edges per pass (8 lanes each), u indices
// buffered 32-at-a-time, K gather software-pipelined. Register accumulation;
// one plain store per node, zero atomics.
// ---------------------------------------------------------------------------
__global__ void __launch_bounds__(256) edge_sorted_kernel(int N) {
    int warp = (blockIdx.x * blockDim.x + threadIdx.x) >> 5;
    if (warp >= N) return;
    int lane = threadIdx.x & 31;
    int sub = lane >> 3;   // edge slot within a pass (0..3)
    int lw8 = lane & 7;    // lane within edge group

    int start = g_off[warp];
    int end   = g_off[warp + 1];

    uint4 qv = reinterpret_cast<const uint4*>(g_q8 + (size_t)warp * 128)[lw8];
    const unsigned int* qw = reinterpret_cast<const unsigned int*>(&qv);

    float bs = g_bs;
    int h = lw8 >> 1;
    float bah = g_ba[h];
    float sacc = 0.0f;

    if (start < end) {
        int bufbase = start;
        int myu = (start + lane < end) ? g_su[start + lane] : 0;

        int ui0 = __shfl_sync(0xffffffffu, myu, sub);
        uint4 kv = reinterpret_cast<const uint4*>(g_k8 + (size_t)ui0 * 128)[lw8];

        for (int e0 = start; e0 < end; e0 += 4) {
            uint4 kvn = kv;
            int e0n = e0 + 4;
            if (e0n < end) {
                int reln = e0n - bufbase + sub;   // uniform rollover
                if (reln >= 32) {
                    bufbase += 32;
                    myu = (bufbase + lane < end) ? g_su[bufbase + lane] : 0;
                    reln -= 32;
                }
                int uin = __shfl_sync(0xffffffffu, myu, reln);
                kvn = reinterpret_cast<const uint4*>(g_k8 + (size_t)uin * 128)[lw8];
            }

            const unsigned int* kw = reinterpret_cast<const unsigned int*>(&kv);
            __half2 acc = __float2half2_rn(0.0f);
#pragma unroll
            for (int w = 0; w < 4; w++) {
                acc = __hfma2(fp8x2_to_h2((unsigned short)(qw[w] & 0xffff)),
                              fp8x2_to_h2((unsigned short)(kw[w] & 0xffff)), acc);
                acc = __hfma2(fp8x2_to_h2((unsigned short)(qw[w] >> 16)),
                              fp8x2_to_h2((unsigned short)(kw[w] >> 16)), acc);
            }
            float fa = __low2float(acc) + __high2float(acc);
            fa += __shfl_xor_sync(0xffffffffu, fa, 1);

            float ev = __expf(fmaf(fa, bs, bah));
            if ((e0 + sub) < end && ((lw8 & 1) == 0)) sacc += ev;

            kv = kvn;
        }
    }

    sacc += __shfl_xor_sync(0xffffffffu, sacc, 8);
    sacc += __shfl_xor_sync(0xffffffffu, sacc, 16);
    if (sub == 0 && (lw8 & 1) == 0) {
        g_s[(size_t)warp * 4 + h] = sacc;
    }
}

// Generic fallback (any H, D) — f32 path, one thread per (edge, head)
__global__ void edge_kernel_g(const float* __restrict__ Q,
                              const float* __restrict__ K,
                              const float* __restrict__ a,
                              const float* __restrict__ beta_raw,
                              const int* __restrict__ c,
                              const int* __restrict__ u,
                              int E, int H, int D) {
    long long tid = (long long)blockIdx.x * blockDim.x + threadIdx.x;
    long long total = (long long)E * H;
    if (tid >= total) return;
    int e = (int)(tid / H);
    int h = (int)(tid % H);

    int ci = c[e];
    int ui = u[e];

    const float* q = Q + ((size_t)ci * H + h) * D;
    const float* k = K + ((size_t)ui * H + h) * D;
    float acc = 0.0f;
    for (int d = 0; d < D; d++) acc = fmaf(q[d], k[d], acc);

    float beta = fminf(softplus_f(beta_raw[0]), 10.0f);
    float ell = acc * rsqrtf((float)D) + a[h];
    atomicAdd(&g_s[(size_t)ci * H + h], __expf(beta * ell));
}

// ---------------------------------------------------------------------------
// Kernel C: per-node log + per-graph reduce via block-local smem.
// ---------------------------------------------------------------------------
#define MAX_GH 4096
__global__ void node_kernel_sm(const int* __restrict__ batch,
                               float* __restrict__ out,
                               int N, int H, int gh) {
    __shared__ float sred[MAX_GH];
    for (int i = threadIdx.x; i < gh; i += blockDim.x) sred[i] = 0.0f;
    __syncthreads();

    if (H == 4) {
        for (int n = blockIdx.x * blockDim.x + threadIdx.x; n < N;
             n += gridDim.x * blockDim.x) {
            float4 sv = reinterpret_cast<const float4*>(g_s)[n];
            int g = batch[n];
            float v0 = sv.x > 0.0f ? logf(sv.x) : 0.0f;
            float v1 = sv.y > 0.0f ? logf(sv.y) : 0.0f;
            float v2 = sv.z > 0.0f ? logf(sv.z) : 0.0f;
            float v3 = sv.w > 0.0f ? logf(sv.w) : 0.0f;
            atomicAdd(&sred[g * 4 + 0], v0);
            atomicAdd(&sred[g * 4 + 1], v1);
            atomicAdd(&sred[g * 4 + 2], v2);
            atomicAdd(&sred[g * 4 + 3], v3);
        }
    } else {
        for (int n = blockIdx.x * blockDim.x + threadIdx.x; n < N;
             n += gridDim.x * blockDim.x) {
            int g = batch[n];
            for (int h = 0; h < H; h++) {
                float s = g_s[(size_t)n * H + h];
                float v = s > 0.0f ? logf(s) : 0.0f;
                atomicAdd(&sred[g * H + h], v);
            }
        }
    }
    __syncthreads();
    float coef = g_coef;
    for (int i = threadIdx.x; i < gh; i += blockDim.x) {
        float v = sred[i];
        if (v != 0.0f) atomicAdd(&out[i], coef * v);
    }
}

__global__ void node_kernel_g(const int* __restrict__ batch,
                              float* __restrict__ out,
                              int N, int H) {
    int n = blockIdx.x * blockDim.x + threadIdx.x;
    if (n >= N) return;
    float coef = g_coef;
    int g = batch[n];
    for (int h = 0; h < H; h++) {
        float s = g_s[(size_t)n * H + h];
        float v = s > 0.0f ? logf(s) : 0.0f;
        atomicAdd(&out[g * H + h], coef * v);
    }
}

// ---------------------------------------------------------------------------
// Launch.  Inputs (metadata order):
//   0: G [4,4] f32 (unused)   1: Q2 [N,H,D] f32   2: K2 [N,H,D] f32
//   3: a_2 [H] f32   4: lambda_2_raw [1] f32   5: beta_2_raw [1] f32
//   6: c_2 [E] i32   7: u_2 [E] i32   8: batch [N] i32
// Output: [num_graphs, H] f32
// ---------------------------------------------------------------------------
extern "C" void kernel_launch(void* const* d_in, const int* in_sizes, int n_in,
                              void* d_out, int out_size) {
    const float* Q        = (const float*)d_in[1];
    const float* K        = (const float*)d_in[2];
    const float* a        = (const float*)d_in[3];
    const float* lam_raw  = (const float*)d_in[4];
    const float* beta_raw = (const float*)d_in[5];
    const int*   c        = (const int*)d_in[6];
    const int*   u        = (const int*)d_in[7];
    const int*   batch    = (const int*)d_in[8];
    float*       out      = (float*)d_out;

    int H = in_sizes[3];
    int E = in_sizes[6];
    int N = in_sizes[8];
    long long nhd = in_sizes[1];
    int D = (int)(nhd / ((long long)N * H));

    int s_count = N * H;
    if (s_count > MAX_S) return;

    const int TB = 256;
    bool fast = (H == 4 && D == 32 && nhd <= MAX_NHD && (nhd % 4) == 0 &&
                 N <= MAX_N && E <= MAX_E);

    if (fast) {
        int total4 = (int)(nhd / 4);
        int work = total4;
        if (s_count > work) work = s_count;
        if (out_size > work) work = out_size;
        if (N > work) work = N;
        prep_kernel<<<(work + TB - 1) / TB, TB>>>(Q, K, a, lam_raw, beta_raw,
                                                  out, out_size, s_count, total4,
                                                  N, H, D);

        int et = (E + 3) / 4;  // threads for 4-edge-per-thread kernels
        hist_kernel<<<(et + TB - 1) / TB, TB>>>(c, E);
        scan1_kernel<<<NT_SCAN / TB, TB>>>(N);
        scan2_kernel<<<1, 1024>>>();
        scan3_kernel<<<NT_SCAN / TB, TB>>>(N, E);
        scatter_kernel<<<(et + TB - 1) / TB, TB>>>(c, u, E);

        long long threads = (long long)N * 32;
        int blocks = (int)((threads + TB - 1) / TB);
        edge_sorted_kernel<<<blocks, TB>>>(N);
    } else {
        prep_kernel<<<((s_count > out_size ? s_count : out_size) + TB - 1) / TB, TB>>>(
            Q, K, a, lam_raw, beta_raw, out, out_size, s_count, 0, 0, H, D);
        long long total = (long long)E * H;
        edge_kernel_g<<<(int)((total + TB - 1) / TB), TB>>>(Q, K, a, beta_raw, c, u, E, H, D);
    }

    if (out_size <= MAX_GH) {
        int blocks = (N + TB - 1) / TB;
        if (blocks > 120) blocks = 120;
        node_kernel_sm<<<blocks, TB>>>(batch, out, N, H, out_size);
    } else {
        node_kernel_g<<<(N + TB - 1) / TB, TB>>>(batch, out, N, H);
    }
}

// round 13
// speedup vs baseline: 2.1711x; 1.4931x over previous
#include <cuda_runtime.h>
#include <cuda_fp16.h>
#include <cuda_fp8.h>
#include <stdint.h>
#include <math.h>

// ---------------------------------------------------------------------------
// Static scratch (no runtime allocation allowed).
//   g_s : accumulator. Fast path: N*2 uint words = N*4 f16 exp-sums (offset by
//         C). Generic path: N*H floats. Zeroed as floats either way.
//   g_q8/g_k8 : e4m3 copies of Q2/K2 (row = H*D = 128B = 1 line)
// ---------------------------------------------------------------------------
#define MAX_S   (4 * 1024 * 1024)
#define MAX_NHD (8 * 1024 * 1024)
#define MAX_HB  64
__device__ __align__(16) float g_s[MAX_S];
__device__ unsigned char g_q8[MAX_NHD];
__device__ unsigned char g_k8[MAX_NHD];
__device__ float         g_bs;          // beta / sqrt(D)
__device__ float         g_ba[MAX_HB];  // beta * a[h] - C   (fast path)
__device__ float         g_coef;        // lam / beta
__device__ float         g_cexp;        // C (exp offset, = 3*beta)

__device__ __forceinline__ float softplus_f(float x) {
    return log1pf(expf(x));
}

__device__ __forceinline__ __half2 fp8x2_to_h2(unsigned short s) {
    union { __half2_raw r; __half2 h; } cvt;
    cvt.r = __nv_cvt_fp8x2_to_halfraw2((__nv_fp8x2_storage_t)s, __NV_E4M3);
    return cvt.h;
}

// ---------------------------------------------------------------------------
// Kernel A (fused): zero g_s + out, convert Q/K f32 -> e4m3, precompute
// scalar params (thread 0).
// ---------------------------------------------------------------------------
__global__ void prep_kernel(const float* __restrict__ Q,
                            const float* __restrict__ K,
                            const float* __restrict__ a,
                            const float* __restrict__ lam_raw,
                            const float* __restrict__ beta_raw,
                            float* __restrict__ out,
                            int out_size, int s_count, int total4,
                            int H, int D, int use_offset) {
    int i = blockIdx.x * blockDim.x + threadIdx.x;
    if (i == 0) {
        float beta = fminf(softplus_f(beta_raw[0]), 10.0f);
        float lam  = softplus_f(lam_raw[0]);
        float C    = use_offset ? 3.0f * beta : 0.0f;
        g_bs   = beta * rsqrtf((float)D);
        g_coef = lam / beta;
        g_cexp = C;
        int hb = H < MAX_HB ? H : MAX_HB;
        for (int h = 0; h < hb; h++) g_ba[h] = beta * a[h] - C;
    }
    if (i < s_count) g_s[i] = 0.0f;
    if (i < out_size) out[i] = 0.0f;
    if (i >= total4) return;
    float4 q = reinterpret_cast<const float4*>(Q)[i];
    float4 k = reinterpret_cast<const float4*>(K)[i];
    unsigned int qp =
        (unsigned int)__nv_cvt_float2_to_fp8x2(make_float2(q.x, q.y), __NV_SATFINITE, __NV_E4M3) |
        ((unsigned int)__nv_cvt_float2_to_fp8x2(make_float2(q.z, q.w), __NV_SATFINITE, __NV_E4M3) << 16);
    unsigned int kp =
        (unsigned int)__nv_cvt_float2_to_fp8x2(make_float2(k.x, k.y), __NV_SATFINITE, __NV_E4M3) |
        ((unsigned int)__nv_cvt_float2_to_fp8x2(make_float2(k.z, k.w), __NV_SATFINITE, __NV_E4M3) << 16);
    reinterpret_cast<unsigned int*>(g_q8)[i] = qp;
    reinterpret_cast<unsigned int*>(g_k8)[i] = kp;
}

// ---------------------------------------------------------------------------
// Kernel B (H=4, D=32, fp8): 16 edges per warp, 8 lanes per edge (R8 geometry)
// with f16x2 REDs: heads packed in pairs, TWO 32-bit red.global.add.noftz.f16x2
// per edge instead of FOUR f32 REDs -> LSU RED dispatch halves (no cracking).
// Values are exp(beta*ell - C); node kernel adds C back after the log.
// ---------------------------------------------------------------------------
__global__ void __launch_bounds__(256) edge_kernel_16(const int* __restrict__ c,
                                                      const int* __restrict__ u,
                                                      int E) {
    int warp = (blockIdx.x * blockDim.x + threadIdx.x) >> 5;
    int lane = threadIdx.x & 31;
    int sub = lane >> 3;   // edge slot within a pass (0..3)
    int lw8 = lane & 7;    // lane within edge

    int base = warp * 16;
    if (base >= E) return;

    // lanes 0-15 load c[base+lane], lanes 16-31 load u[base+lane-16]
    int j = lane & 15;
    int idx = base + j;
    if (idx >= E) idx = E - 1;   // clamp; masked at the RED
    int v = (lane < 16) ? c[idx] : u[idx];

    // Prologue: issue all 16 gather pairs (8 LDG.128 per lane, 32 lines/warp)
    uint4 qv[4], kv[4];
    int   cis[4];
    bool  act[4];
#pragma unroll
    for (int p = 0; p < 4; p++) {
        int eoff = p * 4 + sub;
        act[p] = (base + eoff < E);
        int ci = __shfl_sync(0xffffffffu, v, eoff);
        int ui = __shfl_sync(0xffffffffu, v, 16 + eoff);
        cis[p] = ci;
        qv[p] = reinterpret_cast<const uint4*>(g_q8 + (size_t)ci * 128)[lw8];
        kv[p] = reinterpret_cast<const uint4*>(g_k8 + (size_t)ui * 128)[lw8];
    }

    float bs = g_bs;
    int h = lw8 >> 1;           // head held by even lanes
    float bah = g_ba[h];        // beta*a[h] - C
    unsigned int* sh = reinterpret_cast<unsigned int*>(g_s);

#pragma unroll
    for (int p = 0; p < 4; p++) {
        const unsigned int* qw = reinterpret_cast<const unsigned int*>(&qv[p]);
        const unsigned int* kw = reinterpret_cast<const unsigned int*>(&kv[p]);
        __half2 acc = __float2half2_rn(0.0f);
#pragma unroll
        for (int w = 0; w < 4; w++) {
            acc = __hfma2(fp8x2_to_h2((unsigned short)(qw[w] & 0xffff)),
                          fp8x2_to_h2((unsigned short)(kw[w] & 0xffff)), acc);
            acc = __hfma2(fp8x2_to_h2((unsigned short)(qw[w] >> 16)),
                          fp8x2_to_h2((unsigned short)(kw[w] >> 16)), acc);
        }
        float fa = __low2float(acc) + __high2float(acc);
        fa += __shfl_xor_sync(0xffffffffu, fa, 1);   // pair covers one head

        // exp(beta*ell - C) on head-holder (even) lanes
        float ev = __expf(fmaf(fa, bs, bah));

        // pair heads: lane0 <- h1 (from lane2), lane4 <- h3 (from lane6)
        float evp = __shfl_xor_sync(0xffffffffu, ev, 2);

        if (act[p] && (lw8 & 3) == 0) {
            // lw8==0 -> heads {0,1}; lw8==4 -> heads {2,3}
            __half2 pk = __halves2half2(__float2half_rn(ev), __float2half_rn(evp));
            unsigned int pbits = *reinterpret_cast<unsigned int*>(&pk);
            unsigned int* dst = sh + (size_t)cis[p] * 2 + (lw8 >> 2);
            asm volatile("red.global.add.noftz.f16x2 [%0], %1;"
                         :: "l"(dst), "r"(pbits) : "memory");
        }
    }
}

// Generic fallback (any H, D) — f32 path, one thread per (edge, head)
__global__ void edge_kernel_g(const float* __restrict__ Q,
                              const float* __restrict__ K,
                              const float* __restrict__ a,
                              const float* __restrict__ beta_raw,
                              const int* __restrict__ c,
                              const int* __restrict__ u,
                              int E, int H, int D) {
    long long tid = (long long)blockIdx.x * blockDim.x + threadIdx.x;
    long long total = (long long)E * H;
    if (tid >= total) return;
    int e = (int)(tid / H);
    int h = (int)(tid % H);

    int ci = c[e];
    int ui = u[e];

    const float* q = Q + ((size_t)ci * H + h) * D;
    const float* k = K + ((size_t)ui * H + h) * D;
    float acc = 0.0f;
    for (int d = 0; d < D; d++) acc = fmaf(q[d], k[d], acc);

    float beta = fminf(softplus_f(beta_raw[0]), 10.0f);
    float ell = acc * rsqrtf((float)D) + a[h];
    atomicAdd(&g_s[(size_t)ci * H + h], __expf(beta * ell));
}

// ---------------------------------------------------------------------------
// Kernel C (fast, H=4): per-node lse = C + log(s_f16) (0 if empty), smem
// per-graph reduce, one global atomic per (graph,head) per block.
// ---------------------------------------------------------------------------
#define MAX_GH 4096
__global__ void node_kernel_f16(const int* __restrict__ batch,
                                float* __restrict__ out,
                                int N, int gh) {
    __shared__ float sred[MAX_GH];
    for (int i = threadIdx.x; i < gh; i += blockDim.x) sred[i] = 0.0f;
    __syncthreads();

    float C = g_cexp;
    const uint2* sv2 = reinterpret_cast<const uint2*>(g_s);

    for (int n = blockIdx.x * blockDim.x + threadIdx.x; n < N;
         n += gridDim.x * blockDim.x) {
        uint2 w = sv2[n];
        __half2 p01 = *reinterpret_cast<__half2*>(&w.x);
        __half2 p23 = *reinterpret_cast<__half2*>(&w.y);
        float s0 = __low2float(p01),  s1 = __high2float(p01);
        float s2 = __low2float(p23),  s3 = __high2float(p23);
        int g = batch[n];
        float v0 = s0 > 0.0f ? (C + logf(s0)) : 0.0f;
        float v1 = s1 > 0.0f ? (C + logf(s1)) : 0.0f;
        float v2 = s2 > 0.0f ? (C + logf(s2)) : 0.0f;
        float v3 = s3 > 0.0f ? (C + logf(s3)) : 0.0f;
        atomicAdd(&sred[g * 4 + 0], v0);
        atomicAdd(&sred[g * 4 + 1], v1);
        atomicAdd(&sred[g * 4 + 2], v2);
        atomicAdd(&sred[g * 4 + 3], v3);
    }
    __syncthreads();
    float coef = g_coef;
    for (int i = threadIdx.x; i < gh; i += blockDim.x) {
        float v = sred[i];
        if (v != 0.0f) atomicAdd(&out[i], coef * v);
    }
}

// Generic node kernels (f32 g_s)
__global__ void node_kernel_sm(const int* __restrict__ batch,
                               float* __restrict__ out,
                               int N, int H, int gh) {
    __shared__ float sred[MAX_GH];
    for (int i = threadIdx.x; i < gh; i += blockDim.x) sred[i] = 0.0f;
    __syncthreads();
    for (int n = blockIdx.x * blockDim.x + threadIdx.x; n < N;
         n += gridDim.x * blockDim.x) {
        int g = batch[n];
        for (int h = 0; h < H; h++) {
            float s = g_s[(size_t)n * H + h];
            float v = s > 0.0f ? logf(s) : 0.0f;
            atomicAdd(&sred[g * H + h], v);
        }
    }
    __syncthreads();
    float coef = g_coef;
    for (int i = threadIdx.x; i < gh; i += blockDim.x) {
        float v = sred[i];
        if (v != 0.0f) atomicAdd(&out[i], coef * v);
    }
}

__global__ void node_kernel_g(const int* __restrict__ batch,
                              float* __restrict__ out,
                              int N, int H) {
    int n = blockIdx.x * blockDim.x + threadIdx.x;
    if (n >= N) return;
    float coef = g_coef;
    int g = batch[n];
    for (int h = 0; h < H; h++) {
        float s = g_s[(size_t)n * H + h];
        float v = s > 0.0f ? logf(s) : 0.0f;
        atomicAdd(&out[g * H + h], coef * v);
    }
}

// ---------------------------------------------------------------------------
// Launch.  Inputs (metadata order):
//   0: G [4,4] f32 (unused)   1: Q2 [N,H,D] f32   2: K2 [N,H,D] f32
//   3: a_2 [H] f32   4: lambda_2_raw [1] f32   5: beta_2_raw [1] f32
//   6: c_2 [E] i32   7: u_2 [E] i32   8: batch [N] i32
// Output: [num_graphs, H] f32
// ---------------------------------------------------------------------------
extern "C" void kernel_launch(void* const* d_in, const int* in_sizes, int n_in,
                              void* d_out, int out_size) {
    const float* Q        = (const float*)d_in[1];
    const float* K        = (const float*)d_in[2];
    const float* a        = (const float*)d_in[3];
    const float* lam_raw  = (const float*)d_in[4];
    const float* beta_raw = (const float*)d_in[5];
    const int*   c        = (const int*)d_in[6];
    const int*   u        = (const int*)d_in[7];
    const int*   batch    = (const int*)d_in[8];
    float*       out      = (float*)d_out;

    int H = in_sizes[3];
    int E = in_sizes[6];
    int N = in_sizes[8];
    long long nhd = in_sizes[1];
    int D = (int)(nhd / ((long long)N * H));

    int s_count = N * H;
    if (s_count > MAX_S) return;

    const int TB = 256;
    bool fast = (H == 4 && D == 32 && nhd <= MAX_NHD && (nhd % 4) == 0 &&
                 out_size <= MAX_GH);

    if (fast) {
        int total4 = (int)(nhd / 4);
        int work = total4;
        if (s_count > work) work = s_count;
        if (out_size > work) work = out_size;
        prep_kernel<<<(work + TB - 1) / TB, TB>>>(Q, K, a, lam_raw, beta_raw,
                                                  out, out_size, s_count, total4,
                                                  H, D, 1);

        // 16 edges per warp
        long long warps = (E + 15) / 16;
        long long threads = warps * 32;
        int blocks = (int)((threads + TB - 1) / TB);
        edge_kernel_16<<<blocks, TB>>>(c, u, E);

        int nb = (N + TB - 1) / TB;
        if (nb > 120) nb = 120;
        node_kernel_f16<<<nb, TB>>>(batch, out, N, out_size);
    } else {
        prep_kernel<<<((s_count > out_size ? s_count : out_size) + TB - 1) / TB, TB>>>(
            Q, K, a, lam_raw, beta_raw, out, out_size, s_count, 0, H, D, 0);
        long long total = (long long)E * H;
        edge_kernel_g<<<(int)((total + TB - 1) / TB), TB>>>(Q, K, a, beta_raw, c, u, E, H, D);

        if (out_size <= MAX_GH) {
            int nb = (N + TB - 1) / TB;
            if (nb > 120) nb = 120;
            node_kernel_sm<<<nb, TB>>>(batch, out, N, H, out_size);
        } else {
            node_kernel_g<<<(N + TB - 1) / TB, TB>>>(batch, out, N, H);
        }
    }
}

// round 14
// speedup vs baseline: 2.2219x; 1.0234x over previous
#include <cuda_runtime.h>
#include <cuda_fp16.h>
#include <cuda_fp8.h>
#include <stdint.h>
#include <math.h>

// ---------------------------------------------------------------------------
// Static scratch (no runtime allocation allowed).
//   g_s : per-(node,head) exp-sum accumulator (float), 16B-aligned rows (H=4)
//   g_q8/g_k8 : e4m3 copies of Q2/K2 (row = H*D bytes = 128B = 1 line)
//   scalar params precomputed once in prep
// ---------------------------------------------------------------------------
#define MAX_S   (4 * 1024 * 1024)
#define MAX_NHD (8 * 1024 * 1024)
#define MAX_HB  64
__device__ __align__(16) float g_s[MAX_S];
__device__ unsigned char g_q8[MAX_NHD];
__device__ unsigned char g_k8[MAX_NHD];
__device__ float         g_bs;          // beta / sqrt(D)
__device__ float         g_ba[MAX_HB];  // beta * a[h]
__device__ float         g_coef;        // lam / beta

__device__ __forceinline__ float softplus_f(float x) {
    return log1pf(expf(x));
}

__device__ __forceinline__ __half2 fp8x2_to_h2(unsigned short s) {
    union { __half2_raw r; __half2 h; } cvt;
    cvt.r = __nv_cvt_fp8x2_to_halfraw2((__nv_fp8x2_storage_t)s, __NV_E4M3);
    return cvt.h;
}

__device__ __forceinline__ unsigned int cvt8x4(float4 v) {
    return (unsigned int)__nv_cvt_float2_to_fp8x2(make_float2(v.x, v.y), __NV_SATFINITE, __NV_E4M3) |
           ((unsigned int)__nv_cvt_float2_to_fp8x2(make_float2(v.z, v.w), __NV_SATFINITE, __NV_E4M3) << 16);
}

// ---------------------------------------------------------------------------
// Kernel A (fused): zero g_s + out, convert Q/K f32 -> e4m3, precompute
// scalar params (thread 0). Each thread converts TWO float4s of each matrix
// (4 independent LDG.128 in flight -> higher DRAM utilization).
// ---------------------------------------------------------------------------
__global__ void prep_kernel(const float* __restrict__ Q,
                            const float* __restrict__ K,
                            const float* __restrict__ a,
                            const float* __restrict__ lam_raw,
                            const float* __restrict__ beta_raw,
                            float* __restrict__ out,
                            int out_size, int s_count, int total4,
                            int H, int D) {
    int i = blockIdx.x * blockDim.x + threadIdx.x;
    if (i == 0) {
        float beta = fminf(softplus_f(beta_raw[0]), 10.0f);
        float lam  = softplus_f(lam_raw[0]);
        g_bs   = beta * rsqrtf((float)D);
        g_coef = lam / beta;
        int hb = H < MAX_HB ? H : MAX_HB;
        for (int h = 0; h < hb; h++) g_ba[h] = beta * a[h];
    }
    if (i < s_count) g_s[i] = 0.0f;
    if (i < out_size) out[i] = 0.0f;

    int j0 = i * 2;
    if (j0 >= total4) return;
    const float4* Q4 = reinterpret_cast<const float4*>(Q);
    const float4* K4 = reinterpret_cast<const float4*>(K);
    unsigned int* q8 = reinterpret_cast<unsigned int*>(g_q8);
    unsigned int* k8 = reinterpret_cast<unsigned int*>(g_k8);

    if (j0 + 1 < total4) {
        float4 qa = Q4[j0], qb = Q4[j0 + 1];
        float4 ka = K4[j0], kb = K4[j0 + 1];
        uint2 qp, kp;
        qp.x = cvt8x4(qa); qp.y = cvt8x4(qb);
        kp.x = cvt8x4(ka); kp.y = cvt8x4(kb);
        *reinterpret_cast<uint2*>(q8 + j0) = qp;
        *reinterpret_cast<uint2*>(k8 + j0) = kp;
    } else {
        q8[j0] = cvt8x4(Q4[j0]);
        k8[j0] = cvt8x4(K4[j0]);
    }
}

// ---------------------------------------------------------------------------
// Kernel B (H=4, D=32, fp8): 16 edges per warp, 8 lanes per edge (exact R8).
// Lane l: sub = l>>3 selects one of 4 concurrent edges per pass, lw8 = l&7
// covers 16B of the 128B row (LDG.128). All 16 gather pairs (32 lines)
// issued in the prologue. One shfl_xor pairs the two lanes of each head;
// even lanes hold head h = lw8>>1. One MUFU + one scalar f32 RED per
// (edge,head) — proven fastest variant (v4/f16x2 both regressed).
// ---------------------------------------------------------------------------
__global__ void __launch_bounds__(256) edge_kernel_16(const int* __restrict__ c,
                                                      const int* __restrict__ u,
                                                      int E) {
    int warp = (blockIdx.x * blockDim.x + threadIdx.x) >> 5;
    int lane = threadIdx.x & 31;
    int sub = lane >> 3;   // edge slot within a pass (0..3)
    int lw8 = lane & 7;    // lane within edge

    int base = warp * 16;
    if (base >= E) return;

    // lanes 0-15 load c[base+lane], lanes 16-31 load u[base+lane-16]
    int j = lane & 15;
    int idx = base + j;
    if (idx >= E) idx = E - 1;   // clamp; masked at the RED
    int v = (lane < 16) ? c[idx] : u[idx];

    // Prologue: issue all 16 gather pairs (8 LDG.128 per lane, 32 lines/warp)
    uint4 qv[4], kv[4];
    int   cis[4];
    bool  act[4];
#pragma unroll
    for (int p = 0; p < 4; p++) {
        int eoff = p * 4 + sub;
        act[p] = (base + eoff < E);
        int ci = __shfl_sync(0xffffffffu, v, eoff);
        int ui = __shfl_sync(0xffffffffu, v, 16 + eoff);
        cis[p] = ci;
        qv[p] = reinterpret_cast<const uint4*>(g_q8 + (size_t)ci * 128)[lw8];
        kv[p] = reinterpret_cast<const uint4*>(g_k8 + (size_t)ui * 128)[lw8];
    }

    float bs = g_bs;
    int h = lw8 >> 1;
    float bah = g_ba[h];

#pragma unroll
    for (int p = 0; p < 4; p++) {
        const unsigned int* qw = reinterpret_cast<const unsigned int*>(&qv[p]);
        const unsigned int* kw = reinterpret_cast<const unsigned int*>(&kv[p]);
        __half2 acc = __float2half2_rn(0.0f);
#pragma unroll
        for (int w = 0; w < 4; w++) {
            acc = __hfma2(fp8x2_to_h2((unsigned short)(qw[w] & 0xffff)),
                          fp8x2_to_h2((unsigned short)(kw[w] & 0xffff)), acc);
            acc = __hfma2(fp8x2_to_h2((unsigned short)(qw[w] >> 16)),
                          fp8x2_to_h2((unsigned short)(kw[w] >> 16)), acc);
        }
        float fa = __low2float(acc) + __high2float(acc);
        fa += __shfl_xor_sync(0xffffffffu, fa, 1);   // pair covers one head

        // exp on head-holder (even) lanes; odd lanes produce garbage (unused)
        float ev = __expf(fmaf(fa, bs, bah));

        if (act[p] && ((lw8 & 1) == 0)) {
            atomicAdd(&g_s[(size_t)cis[p] * 4 + h], ev);
        }
    }
}

// Generic fallback (any H, D) — f32 path, one thread per (edge, head)
__global__ void edge_kernel_g(const float* __restrict__ Q,
                              const float* __restrict__ K,
                              const float* __restrict__ a,
                              const float* __restrict__ beta_raw,
                              const int* __restrict__ c,
                              const int* __restrict__ u,
                              int E, int H, int D) {
    long long tid = (long long)blockIdx.x * blockDim.x + threadIdx.x;
    long long total = (long long)E * H;
    if (tid >= total) return;
    int e = (int)(tid / H);
    int h = (int)(tid % H);

    int ci = c[e];
    int ui = u[e];

    const float* q = Q + ((size_t)ci * H + h) * D;
    const float* k = K + ((size_t)ui * H + h) * D;
    float acc = 0.0f;
    for (int d = 0; d < D; d++) acc = fmaf(q[d], k[d], acc);

    float beta = fminf(softplus_f(beta_raw[0]), 10.0f);
    float ell = acc * rsqrtf((float)D) + a[h];
    atomicAdd(&g_s[(size_t)ci * H + h], __expf(beta * ell));
}

// ---------------------------------------------------------------------------
// Kernel C: per-node log + per-graph reduce via block-local smem, then one
// global atomic per (graph,head) per block.
// ---------------------------------------------------------------------------
#define MAX_GH 4096
__global__ void node_kernel_sm(const int* __restrict__ batch,
                               float* __restrict__ out,
                               int N, int H, int gh) {
    __shared__ float sred[MAX_GH];
    for (int i = threadIdx.x; i < gh; i += blockDim.x) sred[i] = 0.0f;
    __syncthreads();

    if (H == 4) {
        for (int n = blockIdx.x * blockDim.x + threadIdx.x; n < N;
             n += gridDim.x * blockDim.x) {
            float4 sv = reinterpret_cast<const float4*>(g_s)[n];
            int g = batch[n];
            float v0 = sv.x > 0.0f ? logf(sv.x) : 0.0f;
            float v1 = sv.y > 0.0f ? logf(sv.y) : 0.0f;
            float v2 = sv.z > 0.0f ? logf(sv.z) : 0.0f;
            float v3 = sv.w > 0.0f ? logf(sv.w) : 0.0f;
            atomicAdd(&sred[g * 4 + 0], v0);
            atomicAdd(&sred[g * 4 + 1], v1);
            atomicAdd(&sred[g * 4 + 2], v2);
            atomicAdd(&sred[g * 4 + 3], v3);
        }
    } else {
        for (int n = blockIdx.x * blockDim.x + threadIdx.x; n < N;
             n += gridDim.x * blockDim.x) {
            int g = batch[n];
            for (int h = 0; h < H; h++) {
                float s = g_s[(size_t)n * H + h];
                float v = s > 0.0f ? logf(s) : 0.0f;
                atomicAdd(&sred[g * H + h], v);
            }
        }
    }
    __syncthreads();
    float coef = g_coef;
    for (int i = threadIdx.x; i < gh; i += blockDim.x) {
        float v = sred[i];
        if (v != 0.0f) atomicAdd(&out[i], coef * v);
    }
}

// Fallback: direct global atomics (only if out_size > MAX_GH)
__global__ void node_kernel_g(const int* __restrict__ batch,
                              float* __restrict__ out,
                              int N, int H) {
    int n = blockIdx.x * blockDim.x + threadIdx.x;
    if (n >= N) return;
    float coef = g_coef;
    int g = batch[n];
    for (int h = 0; h < H; h++) {
        float s = g_s[(size_t)n * H + h];
        float v = s > 0.0f ? logf(s) : 0.0f;
        atomicAdd(&out[g * H + h], coef * v);
    }
}

// ---------------------------------------------------------------------------
// Launch.  Inputs (metadata order):
//   0: G [4,4] f32 (unused)   1: Q2 [N,H,D] f32   2: K2 [N,H,D] f32
//   3: a_2 [H] f32   4: lambda_2_raw [1] f32   5: beta_2_raw [1] f32
//   6: c_2 [E] i32   7: u_2 [E] i32   8: batch [N] i32
// Output: [num_graphs, H] f32
// ---------------------------------------------------------------------------
extern "C" void kernel_launch(void* const* d_in, const int* in_sizes, int n_in,
                              void* d_out, int out_size) {
    const float* Q        = (const float*)d_in[1];
    const float* K        = (const float*)d_in[2];
    const float* a        = (const float*)d_in[3];
    const float* lam_raw  = (const float*)d_in[4];
    const float* beta_raw = (const float*)d_in[5];
    const int*   c        = (const int*)d_in[6];
    const int*   u        = (const int*)d_in[7];
    const int*   batch    = (const int*)d_in[8];
    float*       out      = (float*)d_out;

    int H = in_sizes[3];
    int E = in_sizes[6];
    int N = in_sizes[8];
    long long nhd = in_sizes[1];
    int D = (int)(nhd / ((long long)N * H));

    int s_count = N * H;
    if (s_count > MAX_S) return;

    const int TB = 256;
    bool fast = (H == 4 && D == 32 && nhd <= MAX_NHD && (nhd % 4) == 0);

    if (fast) {
        int total4 = (int)(nhd / 4);
        // threads: 2 float4s per thread for conversion; must also cover
        // s_count and out_size for the zeroing side.
        int work = (total4 + 1) / 2;
        if (s_count > work) work = s_count;
        if (out_size > work) work = out_size;
        prep_kernel<<<(work + TB - 1) / TB, TB>>>(Q, K, a, lam_raw, beta_raw,
                                                  out, out_size, s_count, total4, H, D);

        // 16 edges per warp
        long long warps = (E + 15) / 16;
        long long threads = warps * 32;
        int blocks = (int)((threads + TB - 1) / TB);
        edge_kernel_16<<<blocks, TB>>>(c, u, E);
    } else {
        prep_kernel<<<((s_count > out_size ? s_count : out_size) + TB - 1) / TB, TB>>>(
            Q, K, a, lam_raw, beta_raw, out, out_size, s_count, 0, H, D);
        long long total = (long long)E * H;
        edge_kernel_g<<<(int)((total + TB - 1) / TB), TB>>>(Q, K, a, beta_raw, c, u, E, H, D);
    }

    if (out_size <= MAX_GH) {
        int blocks = (N + TB - 1) / TB;
        if (blocks > 96) blocks = 96;
        node_kernel_sm<<<blocks, TB>>>(batch, out, N, H, out_size);
    } else {
        node_kernel_g<<<(N + TB - 1) / TB, TB>>>(batch, out, N, H);
    }
}

// round 15
// speedup vs baseline: 2.2711x; 1.0221x over previous
#include <cuda_runtime.h>
#include <cuda_fp16.h>
#include <cuda_fp8.h>
#include <stdint.h>
#include <math.h>

// ---------------------------------------------------------------------------
// Static scratch (no runtime allocation allowed).
//   g_s : per-(node,head) exp-sum accumulator (float), 16B-aligned rows (H=4)
//   g_q8/g_k8 : e4m3 copies of Q2/K2 (row = H*D bytes = 128B = 1 line)
//   scalar params precomputed once in prep
// ---------------------------------------------------------------------------
#define MAX_S   (4 * 1024 * 1024)
#define MAX_NHD (8 * 1024 * 1024)
#define MAX_HB  64
__device__ __align__(16) float g_s[MAX_S];
__device__ unsigned char g_q8[MAX_NHD];
__device__ unsigned char g_k8[MAX_NHD];
__device__ float         g_bs;          // beta / sqrt(D)
__device__ float         g_ba[MAX_HB];  // beta * a[h]
__device__ float         g_coef;        // lam / beta

__device__ __forceinline__ float softplus_f(float x) {
    return log1pf(expf(x));
}

__device__ __forceinline__ __half2 fp8x2_to_h2(unsigned short s) {
    union { __half2_raw r; __half2 h; } cvt;
    cvt.r = __nv_cvt_fp8x2_to_halfraw2((__nv_fp8x2_storage_t)s, __NV_E4M3);
    return cvt.h;
}

__device__ __forceinline__ unsigned int cvt8x4(float4 v) {
    return (unsigned int)__nv_cvt_float2_to_fp8x2(make_float2(v.x, v.y), __NV_SATFINITE, __NV_E4M3) |
           ((unsigned int)__nv_cvt_float2_to_fp8x2(make_float2(v.z, v.w), __NV_SATFINITE, __NV_E4M3) << 16);
}

// Streaming gather: 16B load that does NOT allocate an L1 line (no reuse to
// keep; avoids serializing on the per-SM L1 fill port).
__device__ __forceinline__ uint4 ldg_stream16(const void* p) {
    uint4 r;
    asm volatile("ld.global.nc.L1::no_allocate.v4.u32 {%0,%1,%2,%3}, [%4];"
                 : "=r"(r.x), "=r"(r.y), "=r"(r.z), "=r"(r.w) : "l"(p));
    return r;
}

// ---------------------------------------------------------------------------
// Kernel A (fused): zero g_s + out, convert Q/K f32 -> e4m3, precompute
// scalar params (thread 0). Two float4s per thread.
// ---------------------------------------------------------------------------
__global__ void prep_kernel(const float* __restrict__ Q,
                            const float* __restrict__ K,
                            const float* __restrict__ a,
                            const float* __restrict__ lam_raw,
                            const float* __restrict__ beta_raw,
                            float* __restrict__ out,
                            int out_size, int s_count, int total4,
                            int H, int D) {
    int i = blockIdx.x * blockDim.x + threadIdx.x;
    if (i == 0) {
        float beta = fminf(softplus_f(beta_raw[0]), 10.0f);
        float lam  = softplus_f(lam_raw[0]);
        g_bs   = beta * rsqrtf((float)D);
        g_coef = lam / beta;
        int hb = H < MAX_HB ? H : MAX_HB;
        for (int h = 0; h < hb; h++) g_ba[h] = beta * a[h];
    }
    if (i < s_count) g_s[i] = 0.0f;
    if (i < out_size) out[i] = 0.0f;

    int j0 = i * 2;
    if (j0 >= total4) return;
    const float4* Q4 = reinterpret_cast<const float4*>(Q);
    const float4* K4 = reinterpret_cast<const float4*>(K);
    unsigned int* q8 = reinterpret_cast<unsigned int*>(g_q8);
    unsigned int* k8 = reinterpret_cast<unsigned int*>(g_k8);

    if (j0 + 1 < total4) {
        float4 qa = Q4[j0], qb = Q4[j0 + 1];
        float4 ka = K4[j0], kb = K4[j0 + 1];
        uint2 qp, kp;
        qp.x = cvt8x4(qa); qp.y = cvt8x4(qb);
        kp.x = cvt8x4(ka); kp.y = cvt8x4(kb);
        *reinterpret_cast<uint2*>(q8 + j0) = qp;
        *reinterpret_cast<uint2*>(k8 + j0) = kp;
    } else {
        q8[j0] = cvt8x4(Q4[j0]);
        k8[j0] = cvt8x4(K4[j0]);
    }
}

// ---------------------------------------------------------------------------
// Kernel B (H=4, D=32, fp8): 16 edges per warp, 8 lanes per edge (R8 layout)
// with L1-no-allocate streaming gathers.
// ---------------------------------------------------------------------------
__global__ void __launch_bounds__(256) edge_kernel_16(const int* __restrict__ c,
                                                      const int* __restrict__ u,
                                                      int E) {
    int warp = (blockIdx.x * blockDim.x + threadIdx.x) >> 5;
    int lane = threadIdx.x & 31;
    int sub = lane >> 3;   // edge slot within a pass (0..3)
    int lw8 = lane & 7;    // lane within edge

    int base = warp * 16;
    if (base >= E) return;

    // lanes 0-15 load c[base+lane], lanes 16-31 load u[base+lane-16]
    int j = lane & 15;
    int idx = base + j;
    if (idx >= E) idx = E - 1;   // clamp; masked at the RED
    int v = (lane < 16) ? c[idx] : u[idx];

    // Prologue: issue all 16 gather pairs (8 streaming LDG.128 per lane)
    uint4 qv[4], kv[4];
    int   cis[4];
    bool  act[4];
#pragma unroll
    for (int p = 0; p < 4; p++) {
        int eoff = p * 4 + sub;
        act[p] = (base + eoff < E);
        int ci = __shfl_sync(0xffffffffu, v, eoff);
        int ui = __shfl_sync(0xffffffffu, v, 16 + eoff);
        cis[p] = ci;
        qv[p] = ldg_stream16(g_q8 + (size_t)ci * 128 + lw8 * 16);
        kv[p] = ldg_stream16(g_k8 + (size_t)ui * 128 + lw8 * 16);
    }

    float bs = g_bs;
    int h = lw8 >> 1;
    float bah = g_ba[h];

#pragma unroll
    for (int p = 0; p < 4; p++) {
        const unsigned int* qw = reinterpret_cast<const unsigned int*>(&qv[p]);
        const unsigned int* kw = reinterpret_cast<const unsigned int*>(&kv[p]);
        __half2 acc = __float2half2_rn(0.0f);
#pragma unroll
        for (int w = 0; w < 4; w++) {
            acc = __hfma2(fp8x2_to_h2((unsigned short)(qw[w] & 0xffff)),
                          fp8x2_to_h2((unsigned short)(kw[w] & 0xffff)), acc);
            acc = __hfma2(fp8x2_to_h2((unsigned short)(qw[w] >> 16)),
                          fp8x2_to_h2((unsigned short)(kw[w] >> 16)), acc);
        }
        float fa = __low2float(acc) + __high2float(acc);
        fa += __shfl_xor_sync(0xffffffffu, fa, 1);   // pair covers one head

        // exp on head-holder (even) lanes; odd lanes produce garbage (unused)
        float ev = __expf(fmaf(fa, bs, bah));

        if (act[p] && ((lw8 & 1) == 0)) {
            atomicAdd(&g_s[(size_t)cis[p] * 4 + h], ev);
        }
    }
}

// Generic fallback (any H, D) — f32 path, one thread per (edge, head)
__global__ void edge_kernel_g(const float* __restrict__ Q,
                              const float* __restrict__ K,
                              const float* __restrict__ a,
                              const float* __restrict__ beta_raw,
                              const int* __restrict__ c,
                              const int* __restrict__ u,
                              int E, int H, int D) {
    long long tid = (long long)blockIdx.x * blockDim.x + threadIdx.x;
    long long total = (long long)E * H;
    if (tid >= total) return;
    int e = (int)(tid / H);
    int h = (int)(tid % H);

    int ci = c[e];
    int ui = u[e];

    const float* q = Q + ((size_t)ci * H + h) * D;
    const float* k = K + ((size_t)ui * H + h) * D;
    float acc = 0.0f;
    for (int d = 0; d < D; d++) acc = fmaf(q[d], k[d], acc);

    float beta = fminf(softplus_f(beta_raw[0]), 10.0f);
    float ell = acc * rsqrtf((float)D) + a[h];
    atomicAdd(&g_s[(size_t)ci * H + h], __expf(beta * ell));
}

// ---------------------------------------------------------------------------
// Kernel C: per-node log + per-graph reduce via block-local smem, then one
// global atomic per (graph,head) per block.
// ---------------------------------------------------------------------------
#define MAX_GH 4096
__global__ void node_kernel_sm(const int* __restrict__ batch,
                               float* __restrict__ out,
                               int N, int H, int gh) {
    __shared__ float sred[MAX_GH];
    for (int i = threadIdx.x; i < gh; i += blockDim.x) sred[i] = 0.0f;
    __syncthreads();

    if (H == 4) {
        for (int n = blockIdx.x * blockDim.x + threadIdx.x; n < N;
             n += gridDim.x * blockDim.x) {
            float4 sv = reinterpret_cast<const float4*>(g_s)[n];
            int g = batch[n];
            float v0 = sv.x > 0.0f ? logf(sv.x) : 0.0f;
            float v1 = sv.y > 0.0f ? logf(sv.y) : 0.0f;
            float v2 = sv.z > 0.0f ? logf(sv.z) : 0.0f;
            float v3 = sv.w > 0.0f ? logf(sv.w) : 0.0f;
            atomicAdd(&sred[g * 4 + 0], v0);
            atomicAdd(&sred[g * 4 + 1], v1);
            atomicAdd(&sred[g * 4 + 2], v2);
            atomicAdd(&sred[g * 4 + 3], v3);
        }
    } else {
        for (int n = blockIdx.x * blockDim.x + threadIdx.x; n < N;
             n += gridDim.x * blockDim.x) {
            int g = batch[n];
            for (int h = 0; h < H; h++) {
                float s = g_s[(size_t)n * H + h];
                float v = s > 0.0f ? logf(s) : 0.0f;
                atomicAdd(&sred[g * H + h], v);
            }
        }
    }
    __syncthreads();
    float coef = g_coef;
    for (int i = threadIdx.x; i < gh; i += blockDim.x) {
        float v = sred[i];
        if (v != 0.0f) atomicAdd(&out[i], coef * v);
    }
}

// Fallback: direct global atomics (only if out_size > MAX_GH)
__global__ void node_kernel_g(const int* __restrict__ batch,
                              float* __restrict__ out,
                              int N, int H) {
    int n = blockIdx.x * blockDim.x + threadIdx.x;
    if (n >= N) return;
    float coef = g_coef;
    int g = batch[n];
    for (int h = 0; h < H; h++) {
        float s = g_s[(size_t)n * H + h];
        float v = s > 0.0f ? logf(s) : 0.0f;
        atomicAdd(&out[g * H + h], coef * v);
    }
}

// ---------------------------------------------------------------------------
// Launch.  Inputs (metadata order):
//   0: G [4,4] f32 (unused)   1: Q2 [N,H,D] f32   2: K2 [N,H,D] f32
//   3: a_2 [H] f32   4: lambda_2_raw [1] f32   5: beta_2_raw [1] f32
//   6: c_2 [E] i32   7: u_2 [E] i32   8: batch [N] i32
// Output: [num_graphs, H] f32
// ---------------------------------------------------------------------------
extern "C" void kernel_launch(void* const* d_in, const int* in_sizes, int n_in,
                              void* d_out, int out_size) {
    const float* Q        = (const float*)d_in[1];
    const float* K        = (const float*)d_in[2];
    const float* a        = (const float*)d_in[3];
    const float* lam_raw  = (const float*)d_in[4];
    const float* beta_raw = (const float*)d_in[5];
    const int*   c        = (const int*)d_in[6];
    const int*   u        = (const int*)d_in[7];
    const int*   batch    = (const int*)d_in[8];
    float*       out      = (float*)d_out;

    int H = in_sizes[3];
    int E = in_sizes[6];
    int N = in_sizes[8];
    long long nhd = in_sizes[1];
    int D = (int)(nhd / ((long long)N * H));

    int s_count = N * H;
    if (s_count > MAX_S) return;

    const int TB = 256;
    bool fast = (H == 4 && D == 32 && nhd <= MAX_NHD && (nhd % 4) == 0);

    if (fast) {
        int total4 = (int)(nhd / 4);
        int work = (total4 + 1) / 2;
        if (s_count > work) work = s_count;
        if (out_size > work) work = out_size;
        prep_kernel<<<(work + TB - 1) / TB, TB>>>(Q, K, a, lam_raw, beta_raw,
                                                  out, out_size, s_count, total4, H, D);

        // 16 edges per warp
        long long warps = (E + 15) / 16;
        long long threads = warps * 32;
        int blocks = (int)((threads + TB - 1) / TB);
        edge_kernel_16<<<blocks, TB>>>(c, u, E);
    } else {
        prep_kernel<<<((s_count > out_size ? s_count : out_size) + TB - 1) / TB, TB>>>(
            Q, K, a, lam_raw, beta_raw, out, out_size, s_count, 0, H, D);
        long long total = (long long)E * H;
        edge_kernel_g<<<(int)((total + TB - 1) / TB), TB>>>(Q, K, a, beta_raw, c, u, E, H, D);
    }

    if (out_size <= MAX_GH) {
        int blocks = (N + TB - 1) / TB;
        if (blocks > 120) blocks = 120;
        node_kernel_sm<<<blocks, TB>>>(batch, out, N, H, out_size);
    } else {
        node_kernel_g<<<(N + TB - 1) / TB, TB>>>(batch, out, N, H);
    }
}

// round 16
// speedup vs baseline: 2.3638x; 1.0408x over previous
#include <cuda_runtime.h>
#include <cuda_fp16.h>
#include <cuda_fp8.h>
#include <stdint.h>
#include <math.h>

// ---------------------------------------------------------------------------
// Static scratch (no runtime allocation allowed).
//   g_s : per-(node,head) exp-sum accumulator (float), 16B-aligned rows (H=4)
//   g_q8/g_k8 : e4m3 copies of Q2/K2 (row = H*D bytes = 128B = 1 line)
//   scalar params precomputed once in prep
// ---------------------------------------------------------------------------
#define MAX_S   (4 * 1024 * 1024)
#define MAX_NHD (8 * 1024 * 1024)
#define MAX_HB  64
__device__ __align__(16) float g_s[MAX_S];
__device__ unsigned char g_q8[MAX_NHD];
__device__ unsigned char g_k8[MAX_NHD];
__device__ float         g_bs;          // beta / sqrt(D)
__device__ float         g_ba[MAX_HB];  // beta * a[h]
__device__ float         g_coef;        // lam / beta

__device__ __forceinline__ float softplus_f(float x) {
    return log1pf(expf(x));
}

__device__ __forceinline__ __half2 fp8x2_to_h2(unsigned short s) {
    union { __half2_raw r; __half2 h; } cvt;
    cvt.r = __nv_cvt_fp8x2_to_halfraw2((__nv_fp8x2_storage_t)s, __NV_E4M3);
    return cvt.h;
}

__device__ __forceinline__ unsigned int cvt8x4(float4 v) {
    return (unsigned int)__nv_cvt_float2_to_fp8x2(make_float2(v.x, v.y), __NV_SATFINITE, __NV_E4M3) |
           ((unsigned int)__nv_cvt_float2_to_fp8x2(make_float2(v.z, v.w), __NV_SATFINITE, __NV_E4M3) << 16);
}

// ---------------------------------------------------------------------------
// Kernel A (fused): zero g_s + out, convert Q/K f32 -> e4m3, precompute
// scalar params (thread 0). Two float4s per thread (4 LDG.128 in flight).
// ---------------------------------------------------------------------------
__global__ void prep_kernel(const float* __restrict__ Q,
                            const float* __restrict__ K,
                            const float* __restrict__ a,
                            const float* __restrict__ lam_raw,
                            const float* __restrict__ beta_raw,
                            float* __restrict__ out,
                            int out_size, int s_count, int total4,
                            int H, int D) {
    int i = blockIdx.x * blockDim.x + threadIdx.x;
    if (i == 0) {
        float beta = fminf(softplus_f(beta_raw[0]), 10.0f);
        float lam  = softplus_f(lam_raw[0]);
        g_bs   = beta * rsqrtf((float)D);
        g_coef = lam / beta;
        int hb = H < MAX_HB ? H : MAX_HB;
        for (int h = 0; h < hb; h++) g_ba[h] = beta * a[h];
    }
    if (i < s_count) g_s[i] = 0.0f;
    if (i < out_size) out[i] = 0.0f;

    int j0 = i * 2;
    if (j0 >= total4) return;
    const float4* Q4 = reinterpret_cast<const float4*>(Q);
    const float4* K4 = reinterpret_cast<const float4*>(K);
    unsigned int* q8 = reinterpret_cast<unsigned int*>(g_q8);
    unsigned int* k8 = reinterpret_cast<unsigned int*>(g_k8);

    if (j0 + 1 < total4) {
        float4 qa = Q4[j0], qb = Q4[j0 + 1];
        float4 ka = K4[j0], kb = K4[j0 + 1];
        uint2 qp, kp;
        qp.x = cvt8x4(qa); qp.y = cvt8x4(qb);
        kp.x = cvt8x4(ka); kp.y = cvt8x4(kb);
        *reinterpret_cast<uint2*>(q8 + j0) = qp;
        *reinterpret_cast<uint2*>(k8 + j0) = kp;
    } else {
        q8[j0] = cvt8x4(Q4[j0]);
        k8[j0] = cvt8x4(K4[j0]);
    }
}

// ---------------------------------------------------------------------------
// Kernel B (H=4, D=32, fp8) — CHAMPION CONFIG (R8, measured 86.5us):
// 16 edges per warp, 8 lanes per edge. Lane l: sub = l>>3 selects one of 4
// concurrent edges per pass, lw8 = l&7 covers 16B of the 128B row (LDG.128).
// All 16 gather pairs (32 lines) issued in the prologue (MLP ~32/warp).
// One shfl_xor pairs the two lanes of each head; even lanes hold head
// h = lw8>>1. One MUFU + one scalar f32 RED per (edge,head).
// ---------------------------------------------------------------------------
__global__ void __launch_bounds__(256) edge_kernel_16(const int* __restrict__ c,
                                                      const int* __restrict__ u,
                                                      int E) {
    int warp = (blockIdx.x * blockDim.x + threadIdx.x) >> 5;
    int lane = threadIdx.x & 31;
    int sub = lane >> 3;   // edge slot within a pass (0..3)
    int lw8 = lane & 7;    // lane within edge

    int base = warp * 16;
    if (base >= E) return;

    // lanes 0-15 load c[base+lane], lanes 16-31 load u[base+lane-16]
    int j = lane & 15;
    int idx = base + j;
    if (idx >= E) idx = E - 1;   // clamp; masked at the RED
    int v = (lane < 16) ? c[idx] : u[idx];

    // Prologue: issue all 16 gather pairs (8 LDG.128 per lane, 32 lines/warp)
    uint4 qv[4], kv[4];
    int   cis[4];
    bool  act[4];
#pragma unroll
    for (int p = 0; p < 4; p++) {
        int eoff = p * 4 + sub;
        act[p] = (base + eoff < E);
        int ci = __shfl_sync(0xffffffffu, v, eoff);
        int ui = __shfl_sync(0xffffffffu, v, 16 + eoff);
        cis[p] = ci;
        qv[p] = reinterpret_cast<const uint4*>(g_q8 + (size_t)ci * 128)[lw8];
        kv[p] = reinterpret_cast<const uint4*>(g_k8 + (size_t)ui * 128)[lw8];
    }

    float bs = g_bs;
    int h = lw8 >> 1;
    float bah = g_ba[h];

#pragma unroll
    for (int p = 0; p < 4; p++) {
        const unsigned int* qw = reinterpret_cast<const unsigned int*>(&qv[p]);
        const unsigned int* kw = reinterpret_cast<const unsigned int*>(&kv[p]);
        __half2 acc = __float2half2_rn(0.0f);
#pragma unroll
        for (int w = 0; w < 4; w++) {
            acc = __hfma2(fp8x2_to_h2((unsigned short)(qw[w] & 0xffff)),
                          fp8x2_to_h2((unsigned short)(kw[w] & 0xffff)), acc);
            acc = __hfma2(fp8x2_to_h2((unsigned short)(qw[w] >> 16)),
                          fp8x2_to_h2((unsigned short)(kw[w] >> 16)), acc);
        }
        float fa = __low2float(acc) + __high2float(acc);
        fa += __shfl_xor_sync(0xffffffffu, fa, 1);   // pair covers one head

        // exp on head-holder (even) lanes; odd lanes produce garbage (unused)
        float ev = __expf(fmaf(fa, bs, bah));

        if (act[p] && ((lw8 & 1) == 0)) {
            atomicAdd(&g_s[(size_t)cis[p] * 4 + h], ev);
        }
    }
}

// Generic fallback (any H, D) — f32 path, one thread per (edge, head)
__global__ void edge_kernel_g(const float* __restrict__ Q,
                              const float* __restrict__ K,
                              const float* __restrict__ a,
                              const float* __restrict__ beta_raw,
                              const int* __restrict__ c,
                              const int* __restrict__ u,
                              int E, int H, int D) {
    long long tid = (long long)blockIdx.x * blockDim.x + threadIdx.x;
    long long total = (long long)E * H;
    if (tid >= total) return;
    int e = (int)(tid / H);
    int h = (int)(tid % H);

    int ci = c[e];
    int ui = u[e];

    const float* q = Q + ((size_t)ci * H + h) * D;
    const float* k = K + ((size_t)ui * H + h) * D;
    float acc = 0.0f;
    for (int d = 0; d < D; d++) acc = fmaf(q[d], k[d], acc);

    float beta = fminf(softplus_f(beta_raw[0]), 10.0f);
    float ell = acc * rsqrtf((float)D) + a[h];
    atomicAdd(&g_s[(size_t)ci * H + h], __expf(beta * ell));
}

// ---------------------------------------------------------------------------
// Kernel C: per-node log + per-graph reduce via block-local smem, then one
// global atomic per (graph,head) per block.
// ---------------------------------------------------------------------------
#define MAX_GH 4096
__global__ void node_kernel_sm(const int* __restrict__ batch,
                               float* __restrict__ out,
                               int N, int H, int gh) {
    __shared__ float sred[MAX_GH];
    for (int i = threadIdx.x; i < gh; i += blockDim.x) sred[i] = 0.0f;
    __syncthreads();

    if (H == 4) {
        for (int n = blockIdx.x * blockDim.x + threadIdx.x; n < N;
             n += gridDim.x * blockDim.x) {
            float4 sv = reinterpret_cast<const float4*>(g_s)[n];
            int g = batch[n];
            float v0 = sv.x > 0.0f ? logf(sv.x) : 0.0f;
            float v1 = sv.y > 0.0f ? logf(sv.y) : 0.0f;
            float v2 = sv.z > 0.0f ? logf(sv.z) : 0.0f;
            float v3 = sv.w > 0.0f ? logf(sv.w) : 0.0f;
            atomicAdd(&sred[g * 4 + 0], v0);
            atomicAdd(&sred[g * 4 + 1], v1);
            atomicAdd(&sred[g * 4 + 2], v2);
            atomicAdd(&sred[g * 4 + 3], v3);
        }
    } else {
        for (int n = blockIdx.x * blockDim.x + threadIdx.x; n < N;
             n += gridDim.x * blockDim.x) {
            int g = batch[n];
            for (int h = 0; h < H; h++) {
                float s = g_s[(size_t)n * H + h];
                float v = s > 0.0f ? logf(s) : 0.0f;
                atomicAdd(&sred[g * H + h], v);
            }
        }
    }
    __syncthreads();
    float coef = g_coef;
    for (int i = threadIdx.x; i < gh; i += blockDim.x) {
        float v = sred[i];
        if (v != 0.0f) atomicAdd(&out[i], coef * v);
    }
}

// Fallback: direct global atomics (only if out_size > MAX_GH)
__global__ void node_kernel_g(const int* __restrict__ batch,
                              float* __restrict__ out,
                              int N, int H) {
    int n = blockIdx.x * blockDim.x + threadIdx.x;
    if (n >= N) return;
    float coef = g_coef;
    int g = batch[n];
    for (int h = 0; h < H; h++) {
        float s = g_s[(size_t)n * H + h];
        float v = s > 0.0f ? logf(s) : 0.0f;
        atomicAdd(&out[g * H + h], coef * v);
    }
}

// ---------------------------------------------------------------------------
// Launch.  Inputs (metadata order):
//   0: G [4,4] f32 (unused)   1: Q2 [N,H,D] f32   2: K2 [N,H,D] f32
//   3: a_2 [H] f32   4: lambda_2_raw [1] f32   5: beta_2_raw [1] f32
//   6: c_2 [E] i32   7: u_2 [E] i32   8: batch [N] i32
// Output: [num_graphs, H] f32
// ---------------------------------------------------------------------------
extern "C" void kernel_launch(void* const* d_in, const int* in_sizes, int n_in,
                              void* d_out, int out_size) {
    const float* Q        = (const float*)d_in[1];
    const float* K        = (const float*)d_in[2];
    const float* a        = (const float*)d_in[3];
    const float* lam_raw  = (const float*)d_in[4];
    const float* beta_raw = (const float*)d_in[5];
    const int*   c        = (const int*)d_in[6];
    const int*   u        = (const int*)d_in[7];
    const int*   batch    = (const int*)d_in[8];
    float*       out      = (float*)d_out;

    int H = in_sizes[3];
    int E = in_sizes[6];
    int N = in_sizes[8];
    long long nhd = in_sizes[1];
    int D = (int)(nhd / ((long long)N * H));

    int s_count = N * H;
    if (s_count > MAX_S) return;

    const int TB = 256;
    bool fast = (H == 4 && D == 32 && nhd <= MAX_NHD && (nhd % 4) == 0);

    if (fast) {
        int total4 = (int)(nhd / 4);
        int work = (total4 + 1) / 2;
        if (s_count > work) work = s_count;
        if (out_size > work) work = out_size;
        prep_kernel<<<(work + TB - 1) / TB, TB>>>(Q, K, a, lam_raw, beta_raw,
                                                  out, out_size, s_count, total4, H, D);

        // 16 edges per warp
        long long warps = (E + 15) / 16;
        long long threads = warps * 32;
        int blocks = (int)((threads + TB - 1) / TB);
        edge_kernel_16<<<blocks, TB>>>(c, u, E);
    } else {
        prep_kernel<<<((s_count > out_size ? s_count : out_size) + TB - 1) / TB, TB>>>(
            Q, K, a, lam_raw, beta_raw, out, out_size, s_count, 0, H, D);
        long long total = (long long)E * H;
        edge_kernel_g<<<(int)((total + TB - 1) / TB), TB>>>(Q, K, a, beta_raw, c, u, E, H, D);
    }

    if (out_size <= MAX_GH) {
        int blocks = (N + TB - 1) / TB;
        if (blocks > 120) blocks = 120;
        node_kernel_sm<<<blocks, TB>>>(batch, out, N, H, out_size);
    } else {
        node_kernel_g<<<(N + TB - 1) / TB, TB>>>(batch, out, N, H);
    }
}